// round 12
// baseline (speedup 1.0000x reference)
#include <cuda_runtime.h>

// ---------------- problem constants ----------------
#define NUM_VARS 512
#define VAR_DIM  256
#define DIM      1024
#define NTOK     32768          // 8 * 4096
#define TOK_PER_CTA 32
#define NBLK     (NTOK / TOK_PER_CTA)   // 1024
#define KC       16
#define THREADS  256
#define EPSV     1e-7f

// d_out layout: [out | soft_probs | prob_perplexity | gumbel_probs(hard_x)]
#define OUT_OFF   0ULL
#define SOFT_OFF  8388608ULL               // 8*4096*256
#define PPL_OFF   25165824ULL              // + 32768*512
#define HARD_OFF  25165825ULL              // + 1

// ---------------- scratch (no allocations allowed) ----------------
__device__ float g_avg_partial[(size_t)NUM_VARS * NBLK];  // [var][blk]
__device__ float g_mask_partial[NBLK];

// ---------------- packed f32x2 helpers (Blackwell) ----------------
__device__ __forceinline__ void fma2(unsigned long long &acc,
                                     unsigned long long a,
                                     unsigned long long b) {
    asm("fma.rn.f32x2 %0, %1, %2, %0;" : "+l"(acc) : "l"(a), "l"(b));
}
__device__ __forceinline__ unsigned long long dup2(float w) {
    unsigned long long d;
    asm("mov.b64 %0, {%1, %1};" : "=l"(d) : "f"(w));
    return d;
}
__device__ __forceinline__ void unpack2(unsigned long long a, float &lo, float &hi) {
    asm("mov.b64 {%0, %1}, %2;" : "=f"(lo), "=f"(hi) : "l"(a));
}

// =====================================================================
// Fused kernel: GEMM (f32x2) + zero-col0 + mask + argmax + softmax +
//               one-hot + codebook gather + avg-prob partials
// =====================================================================
__global__ __launch_bounds__(THREADS, 2)
void typer_main(const float* __restrict__ x, const float* __restrict__ mask,
                const float* __restrict__ W, const float* __restrict__ cb,
                float* __restrict__ dout)
{
    __shared__ float sW[KC][NUM_VARS];       // 32 KB, [k][var]
    __shared__ float sX[KC][TOK_PER_CTA];    // 2 KB,  [k][tok]  (token pairs contiguous)
    __shared__ float sRedV[2][4];
    __shared__ int   sRedI[2][4];
    __shared__ float sRedS[2][4];
    __shared__ float sPart[2][NUM_VARS];     // 4 KB
    __shared__ float sMsk[2];

    const int tid  = threadIdx.x;
    const int v    = tid & 127;      // var lane 0..127  (owns vars v, v+128, v+256, v+384)
    const int r    = tid >> 7;       // token group 0..1 (owns tokens 16r .. 16r+15)
    const int lane = tid & 31;
    const int wg   = (tid >> 5) & 3; // warp within token group
    const int tok0 = blockIdx.x * TOK_PER_CTA;

    // acc[j][tp] : f32x2 = logits for tokens {16r+2tp, 16r+2tp+1}, var v+128j
    unsigned long long acc[4][8];
    #pragma unroll
    for (int j = 0; j < 4; ++j)
        #pragma unroll
        for (int tp = 0; tp < 8; ++tp) acc[j][tp] = 0ULL;

    // ---------------- GEMM main loop ----------------
    #pragma unroll 1
    for (int kc = 0; kc < DIM; kc += KC) {
        // W chunk, transposed to [k][var].  Coalesced 64B-per-4-lanes gmem reads.
        #pragma unroll
        for (int it = 0; it < 8; ++it) {
            int task = it * THREADS + tid;         // 0..2047
            int var  = task >> 2;
            int q    = task & 3;
            float4 w4 = *reinterpret_cast<const float4*>(
                            W + (size_t)var * DIM + kc + 4 * q);
            sW[4*q + 0][var] = w4.x;
            sW[4*q + 1][var] = w4.y;
            sW[4*q + 2][var] = w4.z;
            sW[4*q + 3][var] = w4.w;
        }
        // x chunk, transposed to [k][tok]
        if (tid < 128) {
            int t = tid >> 2;
            int q = tid & 3;
            float4 x4 = *reinterpret_cast<const float4*>(
                            x + (size_t)(tok0 + t) * DIM + kc + 4 * q);
            sX[4*q + 0][t] = x4.x;
            sX[4*q + 1][t] = x4.y;
            sX[4*q + 2][t] = x4.z;
            sX[4*q + 3][t] = x4.w;
        }
        __syncthreads();

        #pragma unroll
        for (int k = 0; k < KC; ++k) {
            unsigned long long xp[8];
            #pragma unroll
            for (int tp = 0; tp < 8; ++tp)   // LDS.64, warp-uniform (broadcast)
                xp[tp] = *reinterpret_cast<const unsigned long long*>(
                             &sX[k][16 * r + 2 * tp]);
            #pragma unroll
            for (int j = 0; j < 4; ++j) {
                unsigned long long wd = dup2(sW[k][v + 128 * j]); // coalesced LDS.32
                #pragma unroll
                for (int tp = 0; tp < 8; ++tp)
                    fma2(acc[j][tp], xp[tp], wd);                 // 32 FFMA2 / k / thread
            }
        }
        __syncthreads();
    }

    // ---------------- fused epilogue ----------------
    float avgacc[4] = {0.f, 0.f, 0.f, 0.f};
    float msum = 0.f;
    float* soft = dout + SOFT_OFF;
    float* hard = dout + HARD_OFF;
    float* outp = dout + OUT_OFF;

    #pragma unroll 1
    for (int i = 0; i < 16; ++i) {           // both token groups in lockstep
        int t    = 16 * r + i;
        int gtok = tok0 + t;
        float m  = mask[gtok];
        if (v == 0) msum += m;

        // extract logits, zero col 0, apply mask
        float l[4];
        int tp = i >> 1;
        #pragma unroll
        for (int j = 0; j < 4; ++j) {
            float lo, hi; unpack2(acc[j][tp], lo, hi);
            float val = (i & 1) ? hi : lo;
            if (v + 128 * j == 0) val = 0.f;
            l[j] = val * m;
        }

        // local argmax (ascending var order -> strict > keeps first index)
        float bv = l[0]; int bi = v;
        #pragma unroll
        for (int j = 1; j < 4; ++j)
            if (l[j] > bv) { bv = l[j]; bi = v + 128 * j; }
        // warp butterfly argmax, first-index tie-break
        #pragma unroll
        for (int off = 16; off; off >>= 1) {
            float ov = __shfl_xor_sync(0xffffffffu, bv, off);
            int   oi = __shfl_xor_sync(0xffffffffu, bi, off);
            if (ov > bv || (ov == bv && oi < bi)) { bv = ov; bi = oi; }
        }
        if (lane == 0) { sRedV[r][wg] = bv; sRedI[r][wg] = bi; }
        __syncthreads();
        float tmax = sRedV[r][0]; int targ = sRedI[r][0];
        #pragma unroll
        for (int w2 = 1; w2 < 4; ++w2) {
            float ov = sRedV[r][w2]; int oi = sRedI[r][w2];
            if (ov > tmax || (ov == tmax && oi < targ)) { tmax = ov; targ = oi; }
        }

        // softmax
        float e[4]; float s = 0.f;
        #pragma unroll
        for (int j = 0; j < 4; ++j) { e[j] = expf(l[j] - tmax); s += e[j]; }
        #pragma unroll
        for (int off = 16; off; off >>= 1)
            s += __shfl_xor_sync(0xffffffffu, s, off);
        if (lane == 0) sRedS[r][wg] = s;
        __syncthreads();
        float denom = sRedS[r][0] + sRedS[r][1] + sRedS[r][2] + sRedS[r][3];

        size_t rowbase = (size_t)gtok * NUM_VARS;
        #pragma unroll
        for (int j = 0; j < 4; ++j) {
            float p = e[j] / denom;
            soft[rowbase + v + 128 * j] = p;
            hard[rowbase + v + 128 * j] = (v + 128 * j == targ) ? 1.f : 0.f;
            avgacc[j] += p * m;
        }

        // out = codebook[targ] (row 0 of codebook is zeroed)
        float2 c;
        if (targ == 0) { c.x = 0.f; c.y = 0.f; }
        else c = *reinterpret_cast<const float2*>(cb + (size_t)targ * VAR_DIM + 2 * v);
        *reinterpret_cast<float2*>(outp + (size_t)gtok * VAR_DIM + 2 * v) = c;
    }

    // per-CTA partials (no atomics)
    #pragma unroll
    for (int j = 0; j < 4; ++j) sPart[r][v + 128 * j] = avgacc[j];
    if (v == 0) sMsk[r] = msum;
    __syncthreads();
    #pragma unroll
    for (int j = 0; j < 2; ++j) {
        int var = tid + 256 * j;
        g_avg_partial[(size_t)var * NBLK + blockIdx.x] =
            sPart[0][var] + sPart[1][var];
    }
    if (tid == 0) g_mask_partial[blockIdx.x] = sMsk[0] + sMsk[1];
}

// =====================================================================
// Finalize: avg_probs reduction + perplexity scalar
// =====================================================================
__global__ void typer_finalize(float* __restrict__ dout)
{
    __shared__ float sred[NUM_VARS];
    int tid = threadIdx.x;                // 512 threads, one per var

    // total mask
    float mloc = g_mask_partial[tid] + g_mask_partial[tid + 512];
    sred[tid] = mloc;
    __syncthreads();
    for (int off = 256; off; off >>= 1) {
        if (tid < off) sred[tid] += sred[tid + off];
        __syncthreads();
    }
    float mtot = sred[0];
    __syncthreads();

    // avg_probs[tid]
    float a = 0.f;
    const float* p = g_avg_partial + (size_t)tid * NBLK;
    #pragma unroll 4
    for (int c = 0; c < NBLK; c += 4) {
        float4 v4 = *reinterpret_cast<const float4*>(p + c);
        a += v4.x + v4.y + v4.z + v4.w;
    }
    a /= mtot;

    float term = a * logf(a + EPSV);
    sred[tid] = term;
    __syncthreads();
    for (int off = 256; off; off >>= 1) {
        if (tid < off) sred[tid] += sred[tid + off];
        __syncthreads();
    }
    if (tid == 0) dout[PPL_OFF] = expf(-sred[0]);
}

// =====================================================================
extern "C" void kernel_launch(void* const* d_in, const int* in_sizes, int n_in,
                              void* d_out, int out_size)
{
    const float* x    = (const float*)d_in[0];   // [8,4096,1024]
    const float* mask = (const float*)d_in[1];   // [8,4096]
    const float* W    = (const float*)d_in[2];   // [512,1024]
    const float* cb   = (const float*)d_in[3];   // [512,256]
    float* out = (float*)d_out;

    typer_main<<<NBLK, THREADS>>>(x, mask, W, cb, out);
    typer_finalize<<<1, NUM_VARS>>>(out);
}

// round 13
// speedup vs baseline: 1.0007x; 1.0007x over previous
#include <cuda_runtime.h>

// ---------------- problem constants ----------------
#define NUM_VARS 512
#define VAR_DIM  256
#define DIM      1024
#define NTOK     32768          // 8 * 4096
#define TOK_PER_CTA 32
#define NBLK     (NTOK / TOK_PER_CTA)   // 1024
#define KC       16
#define THREADS  256
#define EPSV     1e-7f

// d_out layout: [out | soft_probs | prob_perplexity | gumbel_probs(hard_x)]
#define OUT_OFF   0ULL
#define SOFT_OFF  8388608ULL               // 8*4096*256
#define PPL_OFF   25165824ULL              // + 32768*512
#define HARD_OFF  25165825ULL              // + 1

// ---------------- scratch (no allocations allowed) ----------------
__device__ float g_avg_partial[(size_t)NUM_VARS * NBLK];  // [var][blk]
__device__ float g_mask_partial[NBLK];

// ---------------- packed f32x2 helpers (Blackwell) ----------------
__device__ __forceinline__ void fma2(unsigned long long &acc,
                                     unsigned long long a,
                                     unsigned long long b) {
    asm("fma.rn.f32x2 %0, %1, %2, %0;" : "+l"(acc) : "l"(a), "l"(b));
}
__device__ __forceinline__ unsigned long long dup2(float w) {
    unsigned long long d;
    asm("mov.b64 %0, {%1, %1};" : "=l"(d) : "f"(w));
    return d;
}
__device__ __forceinline__ void unpack2(unsigned long long a, float &lo, float &hi) {
    asm("mov.b64 {%0, %1}, %2;" : "=f"(lo), "=f"(hi) : "l"(a));
}

// =====================================================================
// Fused kernel: GEMM (f32x2) + zero-col0 + mask + argmax + softmax +
//               one-hot + codebook gather + avg-prob partials
// =====================================================================
__global__ __launch_bounds__(THREADS, 2)
void typer_main(const float* __restrict__ x, const float* __restrict__ mask,
                const float* __restrict__ W, const float* __restrict__ cb,
                float* __restrict__ dout)
{
    __shared__ float sW[KC][NUM_VARS];       // 32 KB, [k][var]
    __shared__ float sX[KC][TOK_PER_CTA];    // 2 KB,  [k][tok]  (token pairs contiguous)
    __shared__ float sRedV[2][4];
    __shared__ int   sRedI[2][4];
    __shared__ float sRedS[2][4];
    __shared__ float sPart[2][NUM_VARS];     // 4 KB
    __shared__ float sMsk[2];

    const int tid  = threadIdx.x;
    const int v    = tid & 127;      // var lane 0..127  (owns vars v, v+128, v+256, v+384)
    const int r    = tid >> 7;       // token group 0..1 (owns tokens 16r .. 16r+15)
    const int lane = tid & 31;
    const int wg   = (tid >> 5) & 3; // warp within token group
    const int tok0 = blockIdx.x * TOK_PER_CTA;

    // acc[j][tp] : f32x2 = logits for tokens {16r+2tp, 16r+2tp+1}, var v+128j
    unsigned long long acc[4][8];
    #pragma unroll
    for (int j = 0; j < 4; ++j)
        #pragma unroll
        for (int tp = 0; tp < 8; ++tp) acc[j][tp] = 0ULL;

    // ---------------- GEMM main loop ----------------
    #pragma unroll 1
    for (int kc = 0; kc < DIM; kc += KC) {
        // W chunk, transposed to [k][var].  Coalesced 64B-per-4-lanes gmem reads.
        #pragma unroll
        for (int it = 0; it < 8; ++it) {
            int task = it * THREADS + tid;         // 0..2047
            int var  = task >> 2;
            int q    = task & 3;
            float4 w4 = *reinterpret_cast<const float4*>(
                            W + (size_t)var * DIM + kc + 4 * q);
            sW[4*q + 0][var] = w4.x;
            sW[4*q + 1][var] = w4.y;
            sW[4*q + 2][var] = w4.z;
            sW[4*q + 3][var] = w4.w;
        }
        // x chunk, transposed to [k][tok]
        if (tid < 128) {
            int t = tid >> 2;
            int q = tid & 3;
            float4 x4 = *reinterpret_cast<const float4*>(
                            x + (size_t)(tok0 + t) * DIM + kc + 4 * q);
            sX[4*q + 0][t] = x4.x;
            sX[4*q + 1][t] = x4.y;
            sX[4*q + 2][t] = x4.z;
            sX[4*q + 3][t] = x4.w;
        }
        __syncthreads();

        #pragma unroll
        for (int k = 0; k < KC; ++k) {
            unsigned long long xp[8];
            #pragma unroll
            for (int tp = 0; tp < 8; ++tp)   // LDS.64, warp-uniform (broadcast)
                xp[tp] = *reinterpret_cast<const unsigned long long*>(
                             &sX[k][16 * r + 2 * tp]);
            #pragma unroll
            for (int j = 0; j < 4; ++j) {
                unsigned long long wd = dup2(sW[k][v + 128 * j]); // coalesced LDS.32
                #pragma unroll
                for (int tp = 0; tp < 8; ++tp)
                    fma2(acc[j][tp], xp[tp], wd);                 // 32 FFMA2 / k / thread
            }
        }
        __syncthreads();
    }

    // ---------------- fused epilogue ----------------
    float avgacc[4] = {0.f, 0.f, 0.f, 0.f};
    float msum = 0.f;
    float* soft = dout + SOFT_OFF;
    float* hard = dout + HARD_OFF;
    float* outp = dout + OUT_OFF;

    #pragma unroll 1
    for (int i = 0; i < 16; ++i) {           // both token groups in lockstep
        int t    = 16 * r + i;
        int gtok = tok0 + t;
        float m  = mask[gtok];
        if (v == 0) msum += m;

        // extract logits, zero col 0, apply mask
        float l[4];
        int tp = i >> 1;
        #pragma unroll
        for (int j = 0; j < 4; ++j) {
            float lo, hi; unpack2(acc[j][tp], lo, hi);
            float val = (i & 1) ? hi : lo;
            if (v + 128 * j == 0) val = 0.f;
            l[j] = val * m;
        }

        // local argmax (ascending var order -> strict > keeps first index)
        float bv = l[0]; int bi = v;
        #pragma unroll
        for (int j = 1; j < 4; ++j)
            if (l[j] > bv) { bv = l[j]; bi = v + 128 * j; }
        // warp butterfly argmax, first-index tie-break
        #pragma unroll
        for (int off = 16; off; off >>= 1) {
            float ov = __shfl_xor_sync(0xffffffffu, bv, off);
            int   oi = __shfl_xor_sync(0xffffffffu, bi, off);
            if (ov > bv || (ov == bv && oi < bi)) { bv = ov; bi = oi; }
        }
        if (lane == 0) { sRedV[r][wg] = bv; sRedI[r][wg] = bi; }
        __syncthreads();
        float tmax = sRedV[r][0]; int targ = sRedI[r][0];
        #pragma unroll
        for (int w2 = 1; w2 < 4; ++w2) {
            float ov = sRedV[r][w2]; int oi = sRedI[r][w2];
            if (ov > tmax || (ov == tmax && oi < targ)) { tmax = ov; targ = oi; }
        }

        // softmax
        float e[4]; float s = 0.f;
        #pragma unroll
        for (int j = 0; j < 4; ++j) { e[j] = expf(l[j] - tmax); s += e[j]; }
        #pragma unroll
        for (int off = 16; off; off >>= 1)
            s += __shfl_xor_sync(0xffffffffu, s, off);
        if (lane == 0) sRedS[r][wg] = s;
        __syncthreads();
        float denom = sRedS[r][0] + sRedS[r][1] + sRedS[r][2] + sRedS[r][3];

        size_t rowbase = (size_t)gtok * NUM_VARS;
        #pragma unroll
        for (int j = 0; j < 4; ++j) {
            float p = e[j] / denom;
            soft[rowbase + v + 128 * j] = p;
            hard[rowbase + v + 128 * j] = (v + 128 * j == targ) ? 1.f : 0.f;
            avgacc[j] += p * m;
        }

        // out = codebook[targ] (row 0 of codebook is zeroed)
        float2 c;
        if (targ == 0) { c.x = 0.f; c.y = 0.f; }
        else c = *reinterpret_cast<const float2*>(cb + (size_t)targ * VAR_DIM + 2 * v);
        *reinterpret_cast<float2*>(outp + (size_t)gtok * VAR_DIM + 2 * v) = c;
    }

    // per-CTA partials (no atomics)
    #pragma unroll
    for (int j = 0; j < 4; ++j) sPart[r][v + 128 * j] = avgacc[j];
    if (v == 0) sMsk[r] = msum;
    __syncthreads();
    #pragma unroll
    for (int j = 0; j < 2; ++j) {
        int var = tid + 256 * j;
        g_avg_partial[(size_t)var * NBLK + blockIdx.x] =
            sPart[0][var] + sPart[1][var];
    }
    if (tid == 0) g_mask_partial[blockIdx.x] = sMsk[0] + sMsk[1];
}

// =====================================================================
// Finalize: avg_probs reduction + perplexity scalar
// =====================================================================
__global__ void typer_finalize(float* __restrict__ dout)
{
    __shared__ float sred[NUM_VARS];
    int tid = threadIdx.x;                // 512 threads, one per var

    // total mask
    float mloc = g_mask_partial[tid] + g_mask_partial[tid + 512];
    sred[tid] = mloc;
    __syncthreads();
    for (int off = 256; off; off >>= 1) {
        if (tid < off) sred[tid] += sred[tid + off];
        __syncthreads();
    }
    float mtot = sred[0];
    __syncthreads();

    // avg_probs[tid]
    float a = 0.f;
    const float* p = g_avg_partial + (size_t)tid * NBLK;
    #pragma unroll 4
    for (int c = 0; c < NBLK; c += 4) {
        float4 v4 = *reinterpret_cast<const float4*>(p + c);
        a += v4.x + v4.y + v4.z + v4.w;
    }
    a /= mtot;

    float term = a * logf(a + EPSV);
    sred[tid] = term;
    __syncthreads();
    for (int off = 256; off; off >>= 1) {
        if (tid < off) sred[tid] += sred[tid + off];
        __syncthreads();
    }
    if (tid == 0) dout[PPL_OFF] = expf(-sred[0]);
}

// =====================================================================
extern "C" void kernel_launch(void* const* d_in, const int* in_sizes, int n_in,
                              void* d_out, int out_size)
{
    const float* x    = (const float*)d_in[0];   // [8,4096,1024]
    const float* mask = (const float*)d_in[1];   // [8,4096]
    const float* W    = (const float*)d_in[2];   // [512,1024]
    const float* cb   = (const float*)d_in[3];   // [512,256]
    float* out = (float*)d_out;

    typer_main<<<NBLK, THREADS>>>(x, mask, W, cb, out);
    typer_finalize<<<1, NUM_VARS>>>(out);
}

// round 17
// speedup vs baseline: 3.1971x; 3.1947x over previous
#include <cuda_runtime.h>

// ---------------- constants ----------------
#define NV    512
#define VD    256
#define DIM   1024
#define NTOK  32768
#define EPSV  1e-7f
#define GAPT  1e-3f
#define FIXMAX 16384

// d_out layout: [out | soft_probs | prob_perplexity | gumbel_probs(hard_x)]
#define OUT_OFF   0ULL
#define SOFT_OFF  8388608ULL
#define PPL_OFF   25165824ULL
#define HARD_OFF  25165825ULL

// GEMM tiling
#define MT 128
#define NT 128
#define KT 64                   // bf16 k per chunk
#define KTOT 3072
#define NCHUNK (KTOT / KT)      // 48
#define GEMM_SMEM 65536         // 2 stages x (16KB A + 16KB B)

#define SW(o) ((o) ^ (((o) >> 3) & 0x70))

// ---------------- device scratch (no allocations) ----------------
static __device__ __align__(16) unsigned short g_apack[(size_t)NTOK * 2048]; // 128MB
static __device__ __align__(16) unsigned short g_bpack[(size_t)NV * 3072];   // 3MB
static __device__ __align__(16) float g_logits[(size_t)NTOK * NV];           // 64MB
static __device__ float g_avg_partial[256 * NV];
static __device__ float g_mask_partial[256];
static __device__ int   g_fix_cnt;
static __device__ int   g_fix_tok[FIXMAX];
static __device__ int   g_fix_old[FIXMAX];

// ---------------- helpers ----------------
__device__ __forceinline__ unsigned smem_u32(const void* p) {
    unsigned a;
    asm("{ .reg .u64 t; cvta.to.shared.u64 t, %1; cvt.u32.u64 %0, t; }" : "=r"(a) : "l"(p));
    return a;
}
__device__ __forceinline__ void cpa16(unsigned sa, const void* g) {
    unsigned long long ga = (unsigned long long)__cvta_generic_to_global(g);
    asm volatile("cp.async.cg.shared.global [%0], [%1], 16;" :: "r"(sa), "l"(ga) : "memory");
}
// split fp32 pair (e=even k, o=odd k) -> packed hi bf16x2 (trunc) + lo bf16x2 (rn)
__device__ __forceinline__ void split2(float e, float o, unsigned &hp, unsigned &lp) {
    unsigned eb = __float_as_uint(e), ob = __float_as_uint(o);
    asm("prmt.b32 %0, %1, %2, 0x7632;" : "=r"(hp) : "r"(eb), "r"(ob));
    float he = __uint_as_float(eb & 0xFFFF0000u);
    float ho = __uint_as_float(ob & 0xFFFF0000u);
    asm("cvt.rn.bf16x2.f32 %0, %1, %2;" : "=r"(lp) : "f"(o - ho), "f"(e - he));
}

#define LDSM4(r, a) \
    asm volatile("ldmatrix.sync.aligned.m8n8.x4.shared.b16 {%0,%1,%2,%3}, [%4];" \
        : "=r"((r)[0]), "=r"((r)[1]), "=r"((r)[2]), "=r"((r)[3]) : "r"(a))
#define MMA16816(d, a, b0, b1) \
    asm volatile("mma.sync.aligned.m16n8k16.row.col.f32.bf16.bf16.f32 " \
        "{%0,%1,%2,%3}, {%4,%5,%6,%7}, {%8,%9}, {%0,%1,%2,%3};" \
        : "+f"((d)[0]), "+f"((d)[1]), "+f"((d)[2]), "+f"((d)[3]) \
        : "r"((a)[0]), "r"((a)[1]), "r"((a)[2]), "r"((a)[3]), "r"(b0), "r"(b1))

// =====================================================================
// prep_x: pack x -> A'[tok][2048] = [hi | lo].  8192 CTAs x 256 thr.
// =====================================================================
__global__ void prep_x(const float* __restrict__ x)
{
    int gid = blockIdx.x * 256 + threadIdx.x;
    int tok = gid >> 6;
    int k0  = (gid & 63) * 16;
    const float4* src = (const float4*)(x + (size_t)tok * DIM + k0);
    unsigned hp[8], lp[8];
    #pragma unroll
    for (int q = 0; q < 4; ++q) {
        float4 f = src[q];
        split2(f.x, f.y, hp[2*q],   lp[2*q]);
        split2(f.z, f.w, hp[2*q+1], lp[2*q+1]);
    }
    uint4* dh = (uint4*)(g_apack + (size_t)tok * 2048 + k0);
    uint4* dl = (uint4*)(g_apack + (size_t)tok * 2048 + 1024 + k0);
    dh[0] = make_uint4(hp[0], hp[1], hp[2], hp[3]);
    dh[1] = make_uint4(hp[4], hp[5], hp[6], hp[7]);
    dl[0] = make_uint4(lp[0], lp[1], lp[2], lp[3]);
    dl[1] = make_uint4(lp[4], lp[5], lp[6], lp[7]);
}

// =====================================================================
// prep_w: pack W -> B'[var][3072] = [hi | hi | lo].  512 CTAs x 128 thr.
// =====================================================================
__global__ void prep_w(const float* __restrict__ W)
{
    if (blockIdx.x == 0 && threadIdx.x == 0) g_fix_cnt = 0;
    int r = blockIdx.x;
    int k0 = threadIdx.x * 8;
    const float4* src = (const float4*)(W + (size_t)r * DIM + k0);
    unsigned hp[4], lp[4];
    #pragma unroll
    for (int q = 0; q < 2; ++q) {
        float4 f = src[q];
        split2(f.x, f.y, hp[2*q],   lp[2*q]);
        split2(f.z, f.w, hp[2*q+1], lp[2*q+1]);
    }
    uint4 hv = make_uint4(hp[0], hp[1], hp[2], hp[3]);
    uint4 lv = make_uint4(lp[0], lp[1], lp[2], lp[3]);
    *(uint4*)(g_bpack + (size_t)r * 3072 + k0)        = hv;
    *(uint4*)(g_bpack + (size_t)r * 3072 + 1024 + k0) = hv;
    *(uint4*)(g_bpack + (size_t)r * 3072 + 2048 + k0) = lv;
}

// =====================================================================
// gemm_bf16: logits = A' x B'^T  (M=32768, N=512, K=3072 bf16)
// 1024 CTAs (256 M x 4 N), 256 thr, 2 CTAs/SM, 2-stage cp.async
// =====================================================================
__device__ __forceinline__ void g_load_chunk(unsigned sb, int stage, int ch,
                                             int m0, int n0, int tid)
{
    int kc = ch * KT;
    int ac = kc & 2047;       // A column (hi block then lo block)
    // A tile: 128 rows x 128B  (1024 x 16B transfers; 8 per row)
    #pragma unroll
    for (int it = 0; it < 4; ++it) {
        int cidx = it * 256 + tid;          // 0..1023
        int row = cidx >> 3, q = cidx & 7;
        unsigned dst = sb + stage * 16384 + SW(row * 128 + q * 16);
        cpa16(dst, g_apack + (size_t)(m0 + row) * 2048 + ac + q * 8);
    }
    // B tile: 128 rows x 128B
    #pragma unroll
    for (int it = 0; it < 4; ++it) {
        int cidx = it * 256 + tid;
        int row = cidx >> 3, q = cidx & 7;
        unsigned dst = sb + 32768 + stage * 16384 + SW(row * 128 + q * 16);
        cpa16(dst, g_bpack + (size_t)(n0 + row) * 3072 + kc + q * 8);
    }
    asm volatile("cp.async.commit_group;" ::: "memory");
}

__global__ __launch_bounds__(256, 2) void gemm_bf16()
{
    extern __shared__ __align__(1024) char sm[];
    unsigned sb = smem_u32(sm);
    const int tid = threadIdx.x, wid = tid >> 5, lane = tid & 31;
    const int m0 = (blockIdx.x >> 2) * MT;
    const int n0 = (blockIdx.x & 3) * NT;
    const int wm = wid & 3, wn = wid >> 2;      // warp grid 4(M) x 2(N), tile 32x64

    float c[2][8][4];
    #pragma unroll
    for (int mi = 0; mi < 2; ++mi)
        #pragma unroll
        for (int nj = 0; nj < 8; ++nj)
            #pragma unroll
            for (int q = 0; q < 4; ++q) c[mi][nj][q] = 0.f;

    g_load_chunk(sb, 0, 0, m0, n0, tid);

    #pragma unroll 1
    for (int ch = 0; ch < NCHUNK; ++ch) {
        int s = ch & 1;
        if (ch + 1 < NCHUNK) {
            g_load_chunk(sb, s ^ 1, ch + 1, m0, n0, tid);
            asm volatile("cp.async.wait_group 1;" ::: "memory");
        } else {
            asm volatile("cp.async.wait_group 0;" ::: "memory");
        }
        __syncthreads();

        unsigned abase = sb + s * 16384;
        unsigned bbase = sb + 32768 + s * 16384;
        #pragma unroll
        for (int ks = 0; ks < 4; ++ks) {
            unsigned a[2][4], bq[4][4];
            #pragma unroll
            for (int mi = 0; mi < 2; ++mi) {
                unsigned off = (wm * 32 + mi * 16 + (lane & 15)) * 128
                             + ks * 32 + (lane >> 4) * 16;
                LDSM4(a[mi], abase + SW(off));
            }
            #pragma unroll
            for (int nt = 0; nt < 4; ++nt) {
                unsigned off = (wn * 64 + nt * 16 + (lane & 15)) * 128
                             + ks * 32 + (lane >> 4) * 16;
                LDSM4(bq[nt], bbase + SW(off));     // B[n][k] k-contig == col-major: NO trans
            }
            #pragma unroll
            for (int mi = 0; mi < 2; ++mi)
                #pragma unroll
                for (int nj = 0; nj < 8; ++nj)
                    MMA16816(c[mi][nj], a[mi],
                             bq[nj >> 1][nj & 1], bq[nj >> 1][(nj & 1) + 2]);
        }
        __syncthreads();
    }

    // write logits
    #pragma unroll
    for (int mi = 0; mi < 2; ++mi) {
        int r0 = m0 + wm * 32 + mi * 16 + (lane >> 2);
        #pragma unroll
        for (int nj = 0; nj < 8; ++nj) {
            int cc = n0 + wn * 64 + nj * 8 + (lane & 3) * 2;
            *(float2*)(g_logits + (size_t)r0 * NV + cc)       = make_float2(c[mi][nj][0], c[mi][nj][1]);
            *(float2*)(g_logits + (size_t)(r0 + 8) * NV + cc) = make_float2(c[mi][nj][2], c[mi][nj][3]);
        }
    }
}

// =====================================================================
// ep_main: mask/zero-col0/argmax/softmax/one-hot/codebook + partials
// 256 CTAs x 256 thr; 1 warp per token, 16 tokens per warp.
// =====================================================================
__global__ void ep_main(const float* __restrict__ mask, const float* __restrict__ cb,
                        float* __restrict__ dout)
{
    __shared__ float sAvg[8][NV];     // 16KB
    __shared__ float sMask[128];
    const int tid = threadIdx.x, wid = tid >> 5, lane = tid & 31;
    const int b = blockIdx.x, tok0 = b * 128;

    float acc[16];
    #pragma unroll
    for (int j = 0; j < 16; ++j) acc[j] = 0.f;

    #pragma unroll 1
    for (int it = 0; it < 16; ++it) {
        int gtok = tok0 + wid + 8 * it;
        float m = mask[gtok];
        const float4* lp4 = (const float4*)(g_logits + (size_t)gtok * NV + lane * 16);
        float l[16];
        #pragma unroll
        for (int q = 0; q < 4; ++q) {
            float4 f = lp4[q];
            l[4*q] = f.x; l[4*q+1] = f.y; l[4*q+2] = f.z; l[4*q+3] = f.w;
        }
        if (lane == 0) l[0] = 0.f;          // zero col 0
        #pragma unroll
        for (int j = 0; j < 16; ++j) l[j] *= m;

        // lane-local max / argmax / runner-up (ascending col keeps first idx)
        float bm = l[0], b2 = -1e38f; int bi = lane * 16;
        #pragma unroll
        for (int j = 1; j < 16; ++j) {
            if (l[j] > bm) { b2 = bm; bm = l[j]; bi = lane * 16 + j; }
            else if (l[j] > b2) b2 = l[j];
        }
        // butterfly merge
        #pragma unroll
        for (int off = 16; off; off >>= 1) {
            float om = __shfl_xor_sync(0xffffffffu, bm, off);
            int   oi = __shfl_xor_sync(0xffffffffu, bi, off);
            float os = __shfl_xor_sync(0xffffffffu, b2, off);
            if (om > bm)      { b2 = fmaxf(bm, os); bm = om; bi = oi; }
            else if (om < bm) { b2 = fmaxf(b2, om); }
            else              { b2 = bm; if (oi < bi) bi = oi; }   // exact tie
        }
        // denom
        float s = 0.f;
        #pragma unroll
        for (int j = 0; j < 16; ++j) s += __expf(l[j] - bm);
        #pragma unroll
        for (int off = 16; off; off >>= 1)
            s += __shfl_xor_sync(0xffffffffu, s, off);
        float rd = 1.f / s;

        // soft writes (16B aligned) + avg partials
        float* so = dout + SOFT_OFF + (size_t)gtok * NV + lane * 16;
        #pragma unroll
        for (int q = 0; q < 4; ++q) {
            float p0 = __expf(l[4*q]   - bm) * rd;
            float p1 = __expf(l[4*q+1] - bm) * rd;
            float p2 = __expf(l[4*q+2] - bm) * rd;
            float p3 = __expf(l[4*q+3] - bm) * rd;
            ((float4*)so)[q] = make_float4(p0, p1, p2, p3);
            acc[4*q]   += p0 * m; acc[4*q+1] += p1 * m;
            acc[4*q+2] += p2 * m; acc[4*q+3] += p3 * m;
        }
        // hard writes: HARD_OFF is odd -> scalar, coalesced across lanes
        float* ha = dout + HARD_OFF + (size_t)gtok * NV;
        #pragma unroll
        for (int j = 0; j < 16; ++j) {
            int col = lane + 32 * j;
            ha[col] = (col == bi) ? 1.f : 0.f;
        }
        // out = codebook[bi]
        const float4* cb4 = (const float4*)(cb + (size_t)bi * VD);
        float4* op = (float4*)(dout + OUT_OFF + (size_t)gtok * VD + lane * 8);
        float4 v0, v1;
        if (bi == 0) { v0 = make_float4(0,0,0,0); v1 = v0; }
        else         { v0 = cb4[lane * 2]; v1 = cb4[lane * 2 + 1]; }
        op[0] = v0; op[1] = v1;

        if (lane == 0 && bm - b2 < GAPT) {
            int ix = atomicAdd(&g_fix_cnt, 1);
            if (ix < FIXMAX) { g_fix_tok[ix] = gtok; g_fix_old[ix] = bi; }
        }
    }

    #pragma unroll
    for (int j = 0; j < 16; ++j) sAvg[wid][lane * 16 + j] = acc[j];
    if (tid < 128) sMask[tid] = mask[tok0 + tid];
    __syncthreads();
    for (int cc = tid; cc < NV; cc += 256) {
        float a = 0.f;
        #pragma unroll
        for (int w = 0; w < 8; ++w) a += sAvg[w][cc];
        g_avg_partial[b * NV + cc] = a;
    }
    if (tid == 0) {
        float t = 0.f;
        for (int i = 0; i < 128; ++i) t += sMask[i];
        g_mask_partial[b] = t;
    }
}

// =====================================================================
// typer_fin: avg_probs + perplexity  (1 CTA x 512)
// =====================================================================
__global__ void typer_fin(float* __restrict__ dout)
{
    __shared__ float sred[NV];
    int tid = threadIdx.x;
    sred[tid] = (tid < 256) ? g_mask_partial[tid] : 0.f;
    __syncthreads();
    for (int off = 256; off; off >>= 1) {
        if (tid < off) sred[tid] += sred[tid + off];
        __syncthreads();
    }
    float mtot = sred[0];
    __syncthreads();
    float a = 0.f;
    #pragma unroll 8
    for (int b = 0; b < 256; ++b) a += g_avg_partial[b * NV + tid];
    a /= mtot;
    sred[tid] = a * logf(a + EPSV);
    __syncthreads();
    for (int off = 256; off; off >>= 1) {
        if (tid < off) sred[tid] += sred[tid + off];
        __syncthreads();
    }
    if (tid == 0) dout[PPL_OFF] = expf(-sred[0]);
}

// =====================================================================
// typer_fix: exact fp32 recompute for near-tie tokens; patch hard/out
// =====================================================================
__global__ void typer_fix(const float* __restrict__ x, const float* __restrict__ mask,
                          const float* __restrict__ W, const float* __restrict__ cb,
                          float* __restrict__ dout)
{
    __shared__ float sx[DIM];
    __shared__ float sv[256];
    __shared__ int   si[256];
    __shared__ int   sNew;
    int n = g_fix_cnt; if (n > FIXMAX) n = FIXMAX;
    int tid = threadIdx.x;
    const float4* sx4 = (const float4*)sx;

    for (int i = blockIdx.x; i < n; i += gridDim.x) {
        int tok = g_fix_tok[i];
        ((float4*)sx)[tid] = ((const float4*)(x + (size_t)tok * DIM))[tid];
        __syncthreads();
        float m = mask[tok];
        float best = -1e38f; int bi = 0;
        #pragma unroll
        for (int h = 0; h < 2; ++h) {
            int vv = tid + 256 * h;
            const float4* wr = (const float4*)(W + (size_t)vv * DIM);
            float a0 = 0.f, a1 = 0.f, a2 = 0.f, a3 = 0.f;
            #pragma unroll 4
            for (int q = 0; q < 256; q += 4) {
                float4 w0 = wr[q],   x0 = sx4[q];
                float4 w1 = wr[q+1], x1 = sx4[q+1];
                float4 w2 = wr[q+2], x2 = sx4[q+2];
                float4 w3 = wr[q+3], x3 = sx4[q+3];
                a0 = fmaf(x0.w, w0.w, fmaf(x0.z, w0.z, fmaf(x0.y, w0.y, fmaf(x0.x, w0.x, a0))));
                a1 = fmaf(x1.w, w1.w, fmaf(x1.z, w1.z, fmaf(x1.y, w1.y, fmaf(x1.x, w1.x, a1))));
                a2 = fmaf(x2.w, w2.w, fmaf(x2.z, w2.z, fmaf(x2.y, w2.y, fmaf(x2.x, w2.x, a2))));
                a3 = fmaf(x3.w, w3.w, fmaf(x3.z, w3.z, fmaf(x3.y, w3.y, fmaf(x3.x, w3.x, a3))));
            }
            float l = (vv == 0) ? 0.f : ((a0 + a1) + (a2 + a3)) * m;
            if (l > best) { best = l; bi = vv; }
        }
        sv[tid] = best; si[tid] = bi;
        __syncthreads();
        for (int off = 128; off; off >>= 1) {
            if (tid < off) {
                float ov = sv[tid + off]; int oi = si[tid + off];
                if (ov > sv[tid] || (ov == sv[tid] && oi < si[tid])) {
                    sv[tid] = ov; si[tid] = oi;
                }
            }
            __syncthreads();
        }
        int ni = si[0];
        int old = g_fix_old[i];
        if (tid == 0) sNew = (ni != old) ? 1 : 0;
        __syncthreads();
        if (sNew) {
            if (tid == 0) {
                dout[HARD_OFF + (size_t)tok * NV + old] = 0.f;
                dout[HARD_OFF + (size_t)tok * NV + ni]  = 1.f;
            }
            dout[OUT_OFF + (size_t)tok * VD + tid] =
                (ni == 0) ? 0.f : cb[(size_t)ni * VD + tid];
        }
        __syncthreads();
    }
}

// =====================================================================
extern "C" void kernel_launch(void* const* d_in, const int* in_sizes, int n_in,
                              void* d_out, int out_size)
{
    const float* x    = (const float*)d_in[0];
    const float* mask = (const float*)d_in[1];
    const float* W    = (const float*)d_in[2];
    const float* cb   = (const float*)d_in[3];
    float* out = (float*)d_out;

    cudaFuncSetAttribute(gemm_bf16, cudaFuncAttributeMaxDynamicSharedMemorySize, GEMM_SMEM);

    prep_x<<<8192, 256>>>(x);
    prep_w<<<512, 128>>>(W);
    gemm_bf16<<<1024, 256, GEMM_SMEM>>>();
    ep_main<<<256, 256>>>(mask, cb, out);
    typer_fin<<<1, NV>>>(out);
    typer_fix<<<128, 256>>>(x, mask, W, cb, out);
}